// round 1
// baseline (speedup 1.0000x reference)
#include <cuda_runtime.h>
#include <cuda_bf16.h>

// SingleRoIExtractor: FPN RoIAlign (aligned=False / mmdet legacy), out 7x7, sr=2.
// Inputs: feat0 [2,256,200,304], feat1 [2,256,100,152], feat2 [2,256,50,76],
//         feat3 [2,256,25,38], rois [K,5]. Output [K,256,7,7] f32.

#define OUTS   7
#define CH     256
#define PER_ROI (CH * OUTS * OUTS)   // 12544
#define BLK    256
#define BLOCKS_PER_ROI (PER_ROI / BLK)  // 49

__global__ void __launch_bounds__(BLK)
roi_extract_kernel(const float* __restrict__ f0,
                   const float* __restrict__ f1,
                   const float* __restrict__ f2,
                   const float* __restrict__ f3,
                   const float* __restrict__ rois,
                   float* __restrict__ out)
{
    __shared__ float s_x1, s_y1, s_binw, s_binh;
    __shared__ const float* s_base;   // feat + b*C*H*W
    __shared__ int s_H, s_W;

    const int n   = blockIdx.x / BLOCKS_PER_ROI;
    const int blk = blockIdx.x % BLOCKS_PER_ROI;

    if (threadIdx.x == 0) {
        const float rb  = rois[n * 5 + 0];
        const float rx1 = rois[n * 5 + 1];
        const float ry1 = rois[n * 5 + 2];
        const float rx2 = rois[n * 5 + 3];
        const float ry2 = rois[n * 5 + 4];

        // level mapping (image coords)
        const float sc = sqrtf((rx2 - rx1 + 1.0f) * (ry2 - ry1 + 1.0f));
        int lvl = (int)floorf(log2f(sc * (1.0f / 56.0f) + 1e-6f));
        lvl = lvl < 0 ? 0 : (lvl > 3 ? 3 : lvl);

        const float* f; int H, W; float ss;
        if      (lvl == 0) { f = f0; H = 200; W = 304; ss = 0.25f;    }
        else if (lvl == 1) { f = f1; H = 100; W = 152; ss = 0.125f;   }
        else if (lvl == 2) { f = f2; H = 50;  W = 76;  ss = 0.0625f;  }
        else               { f = f3; H = 25;  W = 38;  ss = 0.03125f; }

        const int b = (int)rb;
        const float x1 = rx1 * ss, y1 = ry1 * ss;
        const float x2 = rx2 * ss, y2 = ry2 * ss;
        const float rw = fmaxf(x2 - x1, 1.0f);
        const float rh = fmaxf(y2 - y1, 1.0f);

        s_x1 = x1; s_y1 = y1;
        s_binw = rw * (1.0f / OUTS);
        s_binh = rh * (1.0f / OUTS);
        s_base = f + (size_t)b * CH * H * W;
        s_H = H; s_W = W;
    }
    __syncthreads();

    // local output index within this RoI: (c, ph, pw), pw fastest
    const int local = blk * BLK + threadIdx.x;
    const int c   = local / (OUTS * OUTS);
    const int rem = local - c * (OUTS * OUTS);
    const int ph  = rem / OUTS;
    const int pw  = rem - ph * OUTS;

    const int H = s_H, W = s_W;
    const float Hf = (float)H, Wf = (float)W;
    const float x1 = s_x1, y1 = s_y1, binw = s_binw, binh = s_binh;
    const float* __restrict__ fc = s_base + (size_t)c * H * W;

    float acc = 0.0f;

    #pragma unroll
    for (int iy = 0; iy < 2; ++iy) {
        // g = (ph*2 + iy + 0.5)/2 ; y = y1 + g*bin_h
        const float y = y1 + ((float)(ph * 2 + iy) + 0.5f) * 0.5f * binh;
        if (y < -1.0f || y > Hf) continue;
        const float yc = fminf(fmaxf(y, 0.0f), Hf - 1.0f);
        const int   y0 = (int)yc;           // yc >= 0 -> trunc == floor
        const float ly = yc - (float)y0;
        const int   yA = y0;
        const int   yB = min(y0 + 1, H - 1);
        const float* __restrict__ r0 = fc + (size_t)yA * W;
        const float* __restrict__ r1 = fc + (size_t)yB * W;

        #pragma unroll
        for (int ix = 0; ix < 2; ++ix) {
            const float x = x1 + ((float)(pw * 2 + ix) + 0.5f) * 0.5f * binw;
            if (x < -1.0f || x > Wf) continue;
            const float xc = fminf(fmaxf(x, 0.0f), Wf - 1.0f);
            const int   x0 = (int)xc;
            const float lx = xc - (float)x0;
            const int   xB = min(x0 + 1, W - 1);

            const float v00 = __ldg(r0 + x0);
            const float v01 = __ldg(r0 + xB);
            const float v10 = __ldg(r1 + x0);
            const float v11 = __ldg(r1 + xB);

            const float top = v00 + (v01 - v00) * lx;
            const float bot = v10 + (v11 - v10) * lx;
            acc += top + (bot - top) * ly;
        }
    }

    out[(size_t)n * PER_ROI + local] = acc * 0.25f;
}

extern "C" void kernel_launch(void* const* d_in, const int* in_sizes, int n_in,
                              void* d_out, int out_size)
{
    const float* f0   = (const float*)d_in[0];
    const float* f1   = (const float*)d_in[1];
    const float* f2   = (const float*)d_in[2];
    const float* f3   = (const float*)d_in[3];
    const float* rois = (const float*)d_in[4];
    float* out = (float*)d_out;

    const int K = in_sizes[4] / 5;      // number of RoIs
    const int grid = K * BLOCKS_PER_ROI;

    roi_extract_kernel<<<grid, BLK>>>(f0, f1, f2, f3, rois, out);
}